// round 9
// baseline (speedup 1.0000x reference)
#include <cuda_runtime.h>
#include <cuda_bf16.h>
#include <cuda_fp16.h>
#include <math.h>
#include <stdint.h>

// DeformableSpatialAttention — split-phase fp16 mma.sync edition
//   K0 : pad + fp16 conv weights -> g_wBh[160][120]; biases -> g_bias
//   K1 : channel mean+max reduce (float4, unroll16) -> g_att(8,2,128,128)
//   K2a: conv GEMM (M=64px tiles, fp16 mma.sync) -> g_conv[ch][pix] fp16
//   K2b: deformable sampling per pixel -> g_attmap
//   K3 : out = x * attmap (streaming)

#define Bn   8
#define Cn   256
#define Hn   128
#define Wn   128
#define HW   (Hn*Wn)
#define PIXT (Bn*HW)      // 131072
#define KK   49
#define NOFF 98
#define NCH  147
#define NP   160          // padded N (channels)
#define KS2  120          // k-stride in halves (240B rows)

__device__ float g_att[Bn*2*HW];
__device__ float g_attmap[Bn*HW];
__device__ __align__(16) __half g_wBh[NP*KS2];     // padded fp16 weights [n][k]
__device__ float g_bias[NP];
__device__ __align__(16) __half g_conv[NP*PIXT];   // conv results [ch][pix]

// ================= K0: weight prep =================
__global__ void dsa_prep_kernel(const float* __restrict__ ow, const float* __restrict__ ob,
                                const float* __restrict__ mw, const float* __restrict__ mb){
    int stride = gridDim.x * blockDim.x;
    for (int i = blockIdx.x*blockDim.x + threadIdx.x; i < NP*KS2; i += stride){
        int n = i / KS2;
        int k = i - n*KS2;
        float v = 0.f;
        if (k < NOFF){
            if      (n < NOFF) v = ow[n*NOFF + k];
            else if (n < NCH)  v = mw[(n-NOFF)*NOFF + k];
        }
        g_wBh[i] = __float2half_rn(v);
        if (k == 0)
            g_bias[n] = (n < NOFF) ? ob[n] : (n < NCH) ? mb[n-NOFF] : 0.f;
    }
}

// ================= K1: channel reduce (float4, unroll16) =================
__global__ void dsa_reduce_kernel(const float* __restrict__ x){
    int t  = blockIdx.x * 128 + threadIdx.x;     // 256 blocks x 128 thr
    int b  = t >> 12;
    int p4 = t & 4095;
    const float4* base = (const float4*)x + (size_t)b*(Cn*HW/4) + p4;
    float4 s = make_float4(0.f,0.f,0.f,0.f);
    float4 m = make_float4(-1e30f,-1e30f,-1e30f,-1e30f);
    #pragma unroll 16
    for (int c = 0; c < Cn; c++){
        float4 v = __ldcs(base + c*(HW/4));
        s.x += v.x; s.y += v.y; s.z += v.z; s.w += v.w;
        m.x = fmaxf(m.x, v.x); m.y = fmaxf(m.y, v.y);
        m.z = fmaxf(m.z, v.z); m.w = fmaxf(m.w, v.w);
    }
    const float r = 1.f/256.f;
    float4 sm4 = make_float4(s.x*r, s.y*r, s.z*r, s.w*r);
    ((float4*)g_att)[b*(2*HW/4) + p4]        = sm4;
    ((float4*)g_att)[b*(2*HW/4) + HW/4 + p4] = m;
}

// ================= K2a: conv GEMM =================
// SMEM: A[64][120] half = 15360 ; B[160][120] half = 38400 ; bias 640
#define SMA_A     0
#define SMA_B     15360
#define SMA_BIAS  53760
#define SMA_TOTAL 54400

__global__ __launch_bounds__(256, 4)
void dsa_conv_kernel(){
    extern __shared__ char sm[];
    __half* Ash  = (__half*)(sm + SMA_A);
    __half* Bsh  = (__half*)(sm + SMA_B);
    float* biass = (float*)(sm + SMA_BIAS);

    const int tid  = threadIdx.x;
    const int wid  = tid >> 5;
    const int lane = tid & 31;
    const int g    = lane >> 2;
    const int tig  = lane & 3;

    const int blk = blockIdx.x;           // b(8) x y(128) x xh(2)
    const int xh  = blk & 1;
    const int y   = (blk >> 1) & 127;
    const int b   = blk >> 8;
    const int px0 = xh * 64;

    const float* att0 = g_att + ((b*2 + 0) << 14);
    const float* att1 = g_att + ((b*2 + 1) << 14);

    // ---- im2col A (half) [64 px][120 k] ----
    {
        const int px = tid & 63;
        #pragma unroll
        for (int it = 0; it < 30; it++){
            int k = (tid >> 6) + it*4;          // 0..119
            float v = 0.f;
            if (k < NOFF){
                int c  = (k >= KK) ? 1 : 0;
                int r  = k - c*KK;
                int dy = r / 7;
                int dx = r - dy*7;
                int gy = y + dy - 3;
                int gx = px0 + px + dx - 3;
                if ((unsigned)gy < (unsigned)Hn && (unsigned)gx < (unsigned)Wn){
                    const float* src = c ? att1 : att0;
                    v = __ldg(src + (gy << 7) + gx);
                }
            }
            Ash[px*KS2 + k] = __float2half_rn(v);
        }
    }
    // ---- copy B weights into SMEM ----
    {
        const float4* src = (const float4*)g_wBh;
        float4* dst = (float4*)Bsh;
        #pragma unroll
        for (int i = tid; i < (NP*KS2*2)/16; i += 256) dst[i] = src[i];
    }
    if (tid < NP) biass[tid] = g_bias[tid];
    __syncthreads();

    // ---- warp GEMM: 8 warps = 4(M)x2(N); per pass 16(M)x40(N), K=112 ----
    const int mrow  = (wid & 3) * 16;
    const int nbase = (wid >> 2) * 80;
    const int pixbase = (b << 14) + (y << 7) + px0;

    #pragma unroll 1
    for (int pass = 0; pass < 2; pass++){
        const int ncolp = nbase + pass*40;
        float acc[5][4];
        #pragma unroll
        for (int ni = 0; ni < 5; ni++)
            #pragma unroll
            for (int j = 0; j < 4; j++) acc[ni][j] = 0.f;

        #pragma unroll
        for (int ks = 0; ks < 7; ks++){
            const int k0 = ks*16;
            const uint32_t a0 = *(const uint32_t*)(Ash + (mrow+g  )*KS2 + k0 + 2*tig    );
            const uint32_t a1 = *(const uint32_t*)(Ash + (mrow+8+g)*KS2 + k0 + 2*tig    );
            const uint32_t a2 = *(const uint32_t*)(Ash + (mrow+g  )*KS2 + k0 + 2*tig + 8);
            const uint32_t a3 = *(const uint32_t*)(Ash + (mrow+8+g)*KS2 + k0 + 2*tig + 8);
            #pragma unroll
            for (int ni = 0; ni < 5; ni++){
                const int n0 = ncolp + ni*8;
                const __half* bp = Bsh + (n0+g)*KS2 + k0 + 2*tig;
                uint32_t b0 = *(const uint32_t*)bp;
                uint32_t b1 = *(const uint32_t*)(bp + 8);
                asm volatile(
                    "mma.sync.aligned.m16n8k16.row.col.f32.f16.f16.f32 "
                    "{%0,%1,%2,%3}, {%4,%5,%6,%7}, {%8,%9}, {%0,%1,%2,%3};"
                    : "+f"(acc[ni][0]), "+f"(acc[ni][1]),
                      "+f"(acc[ni][2]), "+f"(acc[ni][3])
                    : "r"(a0), "r"(a1), "r"(a2), "r"(a3), "r"(b0), "r"(b1));
            }
        }

        // ---- epilogue: bias + mask sigmoid -> g_conv[ch][pix] (fp16) ----
        #pragma unroll
        for (int ni = 0; ni < 5; ni++){
            const int n0 = ncolp + ni*8 + 2*tig;
            #pragma unroll
            for (int j = 0; j < 4; j++){
                int ch = n0 + (j & 1);
                int px = mrow + g + ((j >> 1) << 3);
                if (ch < NCH){
                    float v = acc[ni][j] + biass[ch];
                    if (ch >= NOFF) v = 2.f/(1.f + __expf(-v));
                    g_conv[ch*PIXT + pixbase + px] = __float2half_rn(v);
                }
            }
        }
    }
}

// ================= K2b: deformable sampling =================
__device__ __forceinline__ void bilin2(const float* __restrict__ i0,
                                       const float* __restrict__ i1,
                                       float py, float px,
                                       float& s0, float& s1){
    float fy = floorf(py), fx = floorf(px);
    int y0 = (int)fy, x0 = (int)fx;
    int y1 = y0 + 1,  x1 = x0 + 1;
    float wy1 = py - fy, wy0 = 1.f - wy1;
    float wx1 = px - fx, wx0 = 1.f - wx1;
    float w00 = wy0*wx0, w01 = wy0*wx1, w10 = wy1*wx0, w11 = wy1*wx1;
    s0 = 0.f; s1 = 0.f;
    bool yv0 = (unsigned)y0 < (unsigned)Hn, yv1 = (unsigned)y1 < (unsigned)Hn;
    bool xv0 = (unsigned)x0 < (unsigned)Wn, xv1 = (unsigned)x1 < (unsigned)Wn;
    if (yv0 && xv0){ int o = (y0<<7)+x0; s0 += w00*i0[o]; s1 += w00*i1[o]; }
    if (yv0 && xv1){ int o = (y0<<7)+x1; s0 += w01*i0[o]; s1 += w01*i1[o]; }
    if (yv1 && xv0){ int o = (y1<<7)+x0; s0 += w10*i0[o]; s1 += w10*i1[o]; }
    if (yv1 && xv1){ int o = (y1<<7)+x1; s0 += w11*i0[o]; s1 += w11*i1[o]; }
}

__global__ __launch_bounds__(256)
void dsa_deform_kernel(const float* __restrict__ dconv_w){
    const int t  = blockIdx.x * 256 + threadIdx.x;   // 0..131071
    const int b  = t >> 14;
    const int p  = t & 16383;
    const int y  = p >> 7;
    const int px = p & 127;

    const float* att0 = g_att + ((b*2 + 0) << 14);
    const float* att1 = g_att + ((b*2 + 1) << 14);

    float part = 0.f;
    #pragma unroll 2
    for (int kk = 0; kk < KK; kk++){
        float oy = __half2float(g_conv[(2*kk  )*PIXT + t]);
        float ox = __half2float(g_conv[(2*kk+1)*PIXT + t]);
        float mk = __half2float(g_conv[(NOFF+kk)*PIXT + t]);
        float py = (float)(y + kk/7 - 3) + oy;
        float pxx= (float)(px + kk%7 - 3) + ox;
        float s0, s1;
        bilin2(att0, att1, py, pxx, s0, s1);
        part += (s0*__ldg(dconv_w + kk) + s1*__ldg(dconv_w + KK + kk)) * mk;
    }
    g_attmap[t] = 1.f/(1.f + __expf(-part));
}

// ================= K3: out = x * attmap (streaming, R7 form) =================
__global__ void dsa_mul_kernel(const float* __restrict__ x,
                               float* __restrict__ out){
    int gid = blockIdx.x * 256 + threadIdx.x;       // float4 index
    float4 xv = __ldcs((const float4*)x + gid);
    int e   = gid << 2;
    int b   = e >> 22;
    int pix = e & 16383;
    float4 a = *(const float4*)(g_attmap + (b << 14) + pix);
    xv.x *= a.x; xv.y *= a.y; xv.z *= a.z; xv.w *= a.w;
    __stcs((float4*)out + gid, xv);
}

// ================= launch =================
extern "C" void kernel_launch(void* const* d_in, const int* in_sizes, int n_in,
                              void* d_out, int out_size){
    const float* x        = (const float*)d_in[0];
    const float* offset_w = (const float*)d_in[1];
    const float* offset_b = (const float*)d_in[2];
    const float* mod_w    = (const float*)d_in[3];
    const float* mod_b    = (const float*)d_in[4];
    const float* dconv_w  = (const float*)d_in[5];
    float* out = (float*)d_out;

    cudaFuncSetAttribute(dsa_conv_kernel,
                         cudaFuncAttributeMaxDynamicSharedMemorySize, SMA_TOTAL);

    dsa_prep_kernel<<<16, 512>>>(offset_w, offset_b, mod_w, mod_b);
    dsa_reduce_kernel<<<256, 128>>>(x);
    dsa_conv_kernel<<<Bn*Hn*2, 256, SMA_TOTAL>>>();
    dsa_deform_kernel<<<PIXT/256, 256>>>(dconv_w);
    dsa_mul_kernel<<<(Bn*Cn*HW/4)/256, 256>>>(x, out);
}

// round 10
// speedup vs baseline: 1.0011x; 1.0011x over previous
#include <cuda_runtime.h>
#include <cuda_bf16.h>
#include <cuda_fp16.h>
#include <math.h>
#include <stdint.h>

// DeformableSpatialAttention — split-phase fp16 mma.sync, 4-way deform
//   K0 : pad + fp16 conv weights -> g_wBh[160][120]; biases -> g_bias
//   K1 : channel mean+max reduce (float4, unroll16) -> g_att(8,2,128,128)
//   K2a: conv GEMM (M=64px tiles, fp16 mma.sync) -> g_conv[ch][pix] fp16
//   K2b: deformable sampling, 4 lanes per pixel + shfl reduce -> g_attmap
//   K3 : out = x * attmap (streaming)

#define Bn   8
#define Cn   256
#define Hn   128
#define Wn   128
#define HW   (Hn*Wn)
#define PIXT (Bn*HW)      // 131072
#define KK   49
#define NOFF 98
#define NCH  147
#define NP   160          // padded N (channels)
#define KS2  120          // k-stride in halves (240B rows)

__device__ float g_att[Bn*2*HW];
__device__ float g_attmap[Bn*HW];
__device__ __align__(16) __half g_wBh[NP*KS2];     // padded fp16 weights [n][k]
__device__ float g_bias[NP];
__device__ __align__(16) __half g_conv[NP*PIXT];   // conv results [ch][pix]

// ================= K0: weight prep =================
__global__ void dsa_prep_kernel(const float* __restrict__ ow, const float* __restrict__ ob,
                                const float* __restrict__ mw, const float* __restrict__ mb){
    int stride = gridDim.x * blockDim.x;
    for (int i = blockIdx.x*blockDim.x + threadIdx.x; i < NP*KS2; i += stride){
        int n = i / KS2;
        int k = i - n*KS2;
        float v = 0.f;
        if (k < NOFF){
            if      (n < NOFF) v = ow[n*NOFF + k];
            else if (n < NCH)  v = mw[(n-NOFF)*NOFF + k];
        }
        g_wBh[i] = __float2half_rn(v);
        if (k == 0)
            g_bias[n] = (n < NOFF) ? ob[n] : (n < NCH) ? mb[n-NOFF] : 0.f;
    }
}

// ================= K1: channel reduce (float4, unroll16) =================
__global__ void dsa_reduce_kernel(const float* __restrict__ x){
    int t  = blockIdx.x * 128 + threadIdx.x;     // 256 blocks x 128 thr
    int b  = t >> 12;
    int p4 = t & 4095;
    const float4* base = (const float4*)x + (size_t)b*(Cn*HW/4) + p4;
    float4 s = make_float4(0.f,0.f,0.f,0.f);
    float4 m = make_float4(-1e30f,-1e30f,-1e30f,-1e30f);
    #pragma unroll 16
    for (int c = 0; c < Cn; c++){
        float4 v = __ldcs(base + c*(HW/4));
        s.x += v.x; s.y += v.y; s.z += v.z; s.w += v.w;
        m.x = fmaxf(m.x, v.x); m.y = fmaxf(m.y, v.y);
        m.z = fmaxf(m.z, v.z); m.w = fmaxf(m.w, v.w);
    }
    const float r = 1.f/256.f;
    float4 sm4 = make_float4(s.x*r, s.y*r, s.z*r, s.w*r);
    ((float4*)g_att)[b*(2*HW/4) + p4]        = sm4;
    ((float4*)g_att)[b*(2*HW/4) + HW/4 + p4] = m;
}

// ================= K2a: conv GEMM =================
// SMEM: A[64][120] half = 15360 ; B[160][120] half = 38400 ; bias 640
#define SMA_A     0
#define SMA_B     15360
#define SMA_BIAS  53760
#define SMA_TOTAL 54400

__global__ __launch_bounds__(256, 4)
void dsa_conv_kernel(){
    extern __shared__ char sm[];
    __half* Ash  = (__half*)(sm + SMA_A);
    __half* Bsh  = (__half*)(sm + SMA_B);
    float* biass = (float*)(sm + SMA_BIAS);

    const int tid  = threadIdx.x;
    const int wid  = tid >> 5;
    const int lane = tid & 31;
    const int g    = lane >> 2;
    const int tig  = lane & 3;

    const int blk = blockIdx.x;           // b(8) x y(128) x xh(2)
    const int xh  = blk & 1;
    const int y   = (blk >> 1) & 127;
    const int b   = blk >> 8;
    const int px0 = xh * 64;

    const float* att0 = g_att + ((b*2 + 0) << 14);
    const float* att1 = g_att + ((b*2 + 1) << 14);

    // ---- im2col A (half) [64 px][120 k] ----
    {
        const int px = tid & 63;
        #pragma unroll
        for (int it = 0; it < 30; it++){
            int k = (tid >> 6) + it*4;          // 0..119
            float v = 0.f;
            if (k < NOFF){
                int c  = (k >= KK) ? 1 : 0;
                int r  = k - c*KK;
                int dy = r / 7;
                int dx = r - dy*7;
                int gy = y + dy - 3;
                int gx = px0 + px + dx - 3;
                if ((unsigned)gy < (unsigned)Hn && (unsigned)gx < (unsigned)Wn){
                    const float* src = c ? att1 : att0;
                    v = __ldg(src + (gy << 7) + gx);
                }
            }
            Ash[px*KS2 + k] = __float2half_rn(v);
        }
    }
    // ---- copy B weights into SMEM ----
    {
        const float4* src = (const float4*)g_wBh;
        float4* dst = (float4*)Bsh;
        #pragma unroll
        for (int i = tid; i < (NP*KS2*2)/16; i += 256) dst[i] = src[i];
    }
    if (tid < NP) biass[tid] = g_bias[tid];
    __syncthreads();

    // ---- warp GEMM: 8 warps = 4(M)x2(N); per pass 16(M)x40(N), K=112 ----
    const int mrow  = (wid & 3) * 16;
    const int nbase = (wid >> 2) * 80;
    const int pixbase = (b << 14) + (y << 7) + px0;

    #pragma unroll 1
    for (int pass = 0; pass < 2; pass++){
        const int ncolp = nbase + pass*40;
        float acc[5][4];
        #pragma unroll
        for (int ni = 0; ni < 5; ni++)
            #pragma unroll
            for (int j = 0; j < 4; j++) acc[ni][j] = 0.f;

        #pragma unroll
        for (int ks = 0; ks < 7; ks++){
            const int k0 = ks*16;
            const uint32_t a0 = *(const uint32_t*)(Ash + (mrow+g  )*KS2 + k0 + 2*tig    );
            const uint32_t a1 = *(const uint32_t*)(Ash + (mrow+8+g)*KS2 + k0 + 2*tig    );
            const uint32_t a2 = *(const uint32_t*)(Ash + (mrow+g  )*KS2 + k0 + 2*tig + 8);
            const uint32_t a3 = *(const uint32_t*)(Ash + (mrow+8+g)*KS2 + k0 + 2*tig + 8);
            #pragma unroll
            for (int ni = 0; ni < 5; ni++){
                const int n0 = ncolp + ni*8;
                const __half* bp = Bsh + (n0+g)*KS2 + k0 + 2*tig;
                uint32_t b0 = *(const uint32_t*)bp;
                uint32_t b1 = *(const uint32_t*)(bp + 8);
                asm volatile(
                    "mma.sync.aligned.m16n8k16.row.col.f32.f16.f16.f32 "
                    "{%0,%1,%2,%3}, {%4,%5,%6,%7}, {%8,%9}, {%0,%1,%2,%3};"
                    : "+f"(acc[ni][0]), "+f"(acc[ni][1]),
                      "+f"(acc[ni][2]), "+f"(acc[ni][3])
                    : "r"(a0), "r"(a1), "r"(a2), "r"(a3), "r"(b0), "r"(b1));
            }
        }

        // ---- epilogue: bias + mask sigmoid -> g_conv[ch][pix] (fp16) ----
        #pragma unroll
        for (int ni = 0; ni < 5; ni++){
            const int n0 = ncolp + ni*8 + 2*tig;
            #pragma unroll
            for (int j = 0; j < 4; j++){
                int ch = n0 + (j & 1);
                int px = mrow + g + ((j >> 1) << 3);
                if (ch < NCH){
                    float v = acc[ni][j] + biass[ch];
                    if (ch >= NOFF) v = 2.f/(1.f + __expf(-v));
                    g_conv[ch*PIXT + pixbase + px] = __float2half_rn(v);
                }
            }
        }
    }
}

// ================= K2b: deformable sampling (4 lanes / pixel) =================
__device__ __forceinline__ void bilin2(const float* __restrict__ i0,
                                       const float* __restrict__ i1,
                                       float py, float px,
                                       float& s0, float& s1){
    float fy = floorf(py), fx = floorf(px);
    int y0 = (int)fy, x0 = (int)fx;
    int y1 = y0 + 1,  x1 = x0 + 1;
    float wy1 = py - fy, wy0 = 1.f - wy1;
    float wx1 = px - fx, wx0 = 1.f - wx1;
    float w00 = wy0*wx0, w01 = wy0*wx1, w10 = wy1*wx0, w11 = wy1*wx1;
    s0 = 0.f; s1 = 0.f;
    bool yv0 = (unsigned)y0 < (unsigned)Hn, yv1 = (unsigned)y1 < (unsigned)Hn;
    bool xv0 = (unsigned)x0 < (unsigned)Wn, xv1 = (unsigned)x1 < (unsigned)Wn;
    if (yv0 && xv0){ int o = (y0<<7)+x0; s0 += w00*i0[o]; s1 += w00*i1[o]; }
    if (yv0 && xv1){ int o = (y0<<7)+x1; s0 += w01*i0[o]; s1 += w01*i1[o]; }
    if (yv1 && xv0){ int o = (y1<<7)+x0; s0 += w10*i0[o]; s1 += w10*i1[o]; }
    if (yv1 && xv1){ int o = (y1<<7)+x1; s0 += w11*i0[o]; s1 += w11*i1[o]; }
}

__global__ __launch_bounds__(256)
void dsa_deform_kernel(const float* __restrict__ dconv_w){
    const int gt  = blockIdx.x * 256 + threadIdx.x;  // 0..524287
    const int way = gt & 3;
    const int t   = gt >> 2;                         // pixel 0..131071
    const int b   = t >> 14;
    const int p   = t & 16383;
    const int y   = p >> 7;
    const int px  = p & 127;

    const float* att0 = g_att + ((b*2 + 0) << 14);
    const float* att1 = g_att + ((b*2 + 1) << 14);

    float part = 0.f;
    #pragma unroll
    for (int kk = way; kk < KK; kk += 4){
        float oy = __half2float(g_conv[(2*kk  )*PIXT + t]);
        float ox = __half2float(g_conv[(2*kk+1)*PIXT + t]);
        float mk = __half2float(g_conv[(NOFF+kk)*PIXT + t]);
        float py = (float)(y + kk/7 - 3) + oy;
        float pxx= (float)(px + kk%7 - 3) + ox;
        float s0, s1;
        bilin2(att0, att1, py, pxx, s0, s1);
        part += (s0*__ldg(dconv_w + kk) + s1*__ldg(dconv_w + KK + kk)) * mk;
    }
    // reduce over the 4 ways (lanes 4i..4i+3 hold the same pixel)
    part += __shfl_down_sync(0xFFFFFFFFu, part, 2);
    part += __shfl_down_sync(0xFFFFFFFFu, part, 1);
    if (way == 0)
        g_attmap[t] = 1.f/(1.f + __expf(-part));
}

// ================= K3: out = x * attmap (streaming) =================
__global__ void dsa_mul_kernel(const float* __restrict__ x,
                               float* __restrict__ out){
    int gid = blockIdx.x * 256 + threadIdx.x;       // float4 index
    float4 xv = __ldcs((const float4*)x + gid);
    int e   = gid << 2;
    int b   = e >> 22;
    int pix = e & 16383;
    float4 a = *(const float4*)(g_attmap + (b << 14) + pix);
    xv.x *= a.x; xv.y *= a.y; xv.z *= a.z; xv.w *= a.w;
    __stcs((float4*)out + gid, xv);
}

// ================= launch =================
extern "C" void kernel_launch(void* const* d_in, const int* in_sizes, int n_in,
                              void* d_out, int out_size){
    const float* x        = (const float*)d_in[0];
    const float* offset_w = (const float*)d_in[1];
    const float* offset_b = (const float*)d_in[2];
    const float* mod_w    = (const float*)d_in[3];
    const float* mod_b    = (const float*)d_in[4];
    const float* dconv_w  = (const float*)d_in[5];
    float* out = (float*)d_out;

    cudaFuncSetAttribute(dsa_conv_kernel,
                         cudaFuncAttributeMaxDynamicSharedMemorySize, SMA_TOTAL);

    dsa_prep_kernel<<<16, 512>>>(offset_w, offset_b, mod_w, mod_b);
    dsa_reduce_kernel<<<256, 128>>>(x);
    dsa_conv_kernel<<<Bn*Hn*2, 256, SMA_TOTAL>>>();
    dsa_deform_kernel<<<(PIXT*4)/256, 256>>>(dconv_w);
    dsa_mul_kernel<<<(Bn*Cn*HW/4)/256, 256>>>(x, out);
}

// round 11
// speedup vs baseline: 1.0499x; 1.0488x over previous
#include <cuda_runtime.h>
#include <cuda_bf16.h>
#include <cuda_fp16.h>
#include <math.h>
#include <stdint.h>

// DeformableSpatialAttention — split-phase fp16 mma.sync, packed deform
//   K0 : weights->g_wBh, biases->g_bias, tap tables g_tapi/g_tapf
//   K1 : channel mean+max reduce -> g_att (planes) + g_att2 (float2 packed)
//   K2a: conv GEMM (fp16 mma.sync) -> g_off[kk][pix] half2 + g_mask[kk][pix]
//   K2b: deformable sampling, 4 lanes/pixel, float2 gathers -> g_attmap
//   K3 : out = x * attmap (streaming)

#define Bn   8
#define Cn   256
#define Hn   128
#define Wn   128
#define HW   (Hn*Wn)
#define PIXT (Bn*HW)      // 131072
#define KK   49
#define NOFF 98
#define NCH  147
#define NP   160          // padded N (channels)
#define KS2  120          // k-stride in halves (240B rows)

__device__ float  g_att[Bn*2*HW];                  // [b][c][pix] (im2col src)
__device__ float2 g_att2[Bn*HW];                   // [b][pix] = (avg, max)
__device__ float  g_attmap[Bn*HW];
__device__ __align__(16) __half g_wBh[NP*KS2];     // padded fp16 weights [n][k]
__device__ float  g_bias[NP];
__device__ __align__(8) __half2 g_off[KK*PIXT];    // (oy, ox) per tap/pixel
__device__ __half g_mask[KK*PIXT];                 // modulation per tap/pixel
__device__ int    g_tapi[KS2];                     // im2col tap info
__device__ float4 g_tapf[KK];                      // (dy-3, dx-3, w0, w1)

// ================= K0: weight prep + tables =================
__global__ void dsa_prep_kernel(const float* __restrict__ ow, const float* __restrict__ ob,
                                const float* __restrict__ mw, const float* __restrict__ mb,
                                const float* __restrict__ dw){
    int gtid   = blockIdx.x*blockDim.x + threadIdx.x;
    int stride = gridDim.x * blockDim.x;
    for (int i = gtid; i < NP*KS2; i += stride){
        int n = i / KS2;
        int k = i - n*KS2;
        float v = 0.f;
        if (k < NOFF){
            if      (n < NOFF) v = ow[n*NOFF + k];
            else if (n < NCH)  v = mw[(n-NOFF)*NOFF + k];
        }
        g_wBh[i] = __float2half_rn(v);
        if (k == 0)
            g_bias[n] = (n < NOFF) ? ob[n] : (n < NCH) ? mb[n-NOFF] : 0.f;
    }
    if (gtid < KS2){
        int k = gtid;
        if (k < NOFF){
            int c = (k >= KK) ? 1 : 0;
            int r = k - c*KK;
            g_tapi[k] = (c << 16) | ((r/7) << 8) | (r%7);
        } else g_tapi[k] = -1;
    }
    if (gtid < KK){
        g_tapf[gtid] = make_float4((float)(gtid/7) - 3.f, (float)(gtid%7) - 3.f,
                                   dw[gtid], dw[KK + gtid]);
    }
}

// ================= K1: channel reduce (float4, unroll16) =================
__global__ void dsa_reduce_kernel(const float* __restrict__ x){
    int t  = blockIdx.x * 128 + threadIdx.x;     // 256 blocks x 128 thr
    int b  = t >> 12;
    int p4 = t & 4095;
    const float4* base = (const float4*)x + (size_t)b*(Cn*HW/4) + p4;
    float4 s = make_float4(0.f,0.f,0.f,0.f);
    float4 m = make_float4(-1e30f,-1e30f,-1e30f,-1e30f);
    #pragma unroll 16
    for (int c = 0; c < Cn; c++){
        float4 v = __ldcs(base + c*(HW/4));
        s.x += v.x; s.y += v.y; s.z += v.z; s.w += v.w;
        m.x = fmaxf(m.x, v.x); m.y = fmaxf(m.y, v.y);
        m.z = fmaxf(m.z, v.z); m.w = fmaxf(m.w, v.w);
    }
    const float r = 1.f/256.f;
    float4 sm4 = make_float4(s.x*r, s.y*r, s.z*r, s.w*r);
    ((float4*)g_att)[b*(2*HW/4) + p4]        = sm4;
    ((float4*)g_att)[b*(2*HW/4) + HW/4 + p4] = m;
    int pix = (b << 14) + (p4 << 2);
    g_att2[pix    ] = make_float2(sm4.x, m.x);
    g_att2[pix + 1] = make_float2(sm4.y, m.y);
    g_att2[pix + 2] = make_float2(sm4.z, m.z);
    g_att2[pix + 3] = make_float2(sm4.w, m.w);
}

// ================= K2a: conv GEMM =================
// SMEM: A[64][120] half = 15360 ; B[160][120] half = 38400 ; bias 640
#define SMA_A     0
#define SMA_B     15360
#define SMA_BIAS  53760
#define SMA_TOTAL 54400

__global__ __launch_bounds__(256, 4)
void dsa_conv_kernel(){
    extern __shared__ char sm[];
    __half* Ash  = (__half*)(sm + SMA_A);
    __half* Bsh  = (__half*)(sm + SMA_B);
    float* biass = (float*)(sm + SMA_BIAS);

    const int tid  = threadIdx.x;
    const int wid  = tid >> 5;
    const int lane = tid & 31;
    const int g    = lane >> 2;
    const int tig  = lane & 3;

    const int blk = blockIdx.x;           // b(8) x y(128) x xh(2)
    const int xh  = blk & 1;
    const int y   = (blk >> 1) & 127;
    const int b   = blk >> 8;
    const int px0 = xh * 64;

    const float* att0 = g_att + ((b*2 + 0) << 14);
    const float* att1 = g_att + ((b*2 + 1) << 14);

    // ---- im2col A (half) [64 px][120 k] via tap table ----
    {
        const int px = tid & 63;
        #pragma unroll
        for (int it = 0; it < 30; it++){
            int k = (tid >> 6) + it*4;          // 0..119
            int info = __ldg(g_tapi + k);
            float v = 0.f;
            if (info >= 0){
                int c  = info >> 16;
                int dy = (info >> 8) & 255;
                int dx = info & 255;
                int gy = y + dy - 3;
                int gx = px0 + px + dx - 3;
                if ((unsigned)gy < (unsigned)Hn && (unsigned)gx < (unsigned)Wn){
                    const float* src = c ? att1 : att0;
                    v = __ldg(src + (gy << 7) + gx);
                }
            }
            Ash[px*KS2 + k] = __float2half_rn(v);
        }
    }
    // ---- copy B weights into SMEM ----
    {
        const float4* src = (const float4*)g_wBh;
        float4* dst = (float4*)Bsh;
        #pragma unroll
        for (int i = tid; i < (NP*KS2*2)/16; i += 256) dst[i] = src[i];
    }
    if (tid < NP) biass[tid] = g_bias[tid];
    __syncthreads();

    // ---- warp GEMM: 8 warps = 4(M)x2(N); per pass 16(M)x40(N), K=112 ----
    const int mrow  = (wid & 3) * 16;
    const int nbase = (wid >> 2) * 80;
    const int pixbase = (b << 14) + (y << 7) + px0;

    #pragma unroll 1
    for (int pass = 0; pass < 2; pass++){
        const int ncolp = nbase + pass*40;
        float acc[5][4];
        #pragma unroll
        for (int ni = 0; ni < 5; ni++)
            #pragma unroll
            for (int j = 0; j < 4; j++) acc[ni][j] = 0.f;

        #pragma unroll
        for (int ks = 0; ks < 7; ks++){
            const int k0 = ks*16;
            const uint32_t a0 = *(const uint32_t*)(Ash + (mrow+g  )*KS2 + k0 + 2*tig    );
            const uint32_t a1 = *(const uint32_t*)(Ash + (mrow+8+g)*KS2 + k0 + 2*tig    );
            const uint32_t a2 = *(const uint32_t*)(Ash + (mrow+g  )*KS2 + k0 + 2*tig + 8);
            const uint32_t a3 = *(const uint32_t*)(Ash + (mrow+8+g)*KS2 + k0 + 2*tig + 8);
            #pragma unroll
            for (int ni = 0; ni < 5; ni++){
                const int n0 = ncolp + ni*8;
                const __half* bp = Bsh + (n0+g)*KS2 + k0 + 2*tig;
                uint32_t b0 = *(const uint32_t*)bp;
                uint32_t b1 = *(const uint32_t*)(bp + 8);
                asm volatile(
                    "mma.sync.aligned.m16n8k16.row.col.f32.f16.f16.f32 "
                    "{%0,%1,%2,%3}, {%4,%5,%6,%7}, {%8,%9}, {%0,%1,%2,%3};"
                    : "+f"(acc[ni][0]), "+f"(acc[ni][1]),
                      "+f"(acc[ni][2]), "+f"(acc[ni][3])
                    : "r"(a0), "r"(a1), "r"(a2), "r"(a3), "r"(b0), "r"(b1));
            }
        }

        // ---- epilogue: channel-pairs -> g_off (half2) / g_mask ----
        #pragma unroll
        for (int ni = 0; ni < 5; ni++){
            const int n0 = ncolp + ni*8 + 2*tig;     // even
            const int pA = pixbase + mrow + g;       // j=0,1
            const int pB = pA + 8;                   // j=2,3
            if (n0 < NOFF){
                // offset pair: channels (2kk, 2kk+1) = (oy, ox)
                const int kkT = n0 >> 1;
                float b0 = biass[n0], b1 = biass[n0+1];
                g_off[kkT*PIXT + pA] = __floats2half2_rn(acc[ni][0]+b0, acc[ni][1]+b1);
                g_off[kkT*PIXT + pB] = __floats2half2_rn(acc[ni][2]+b0, acc[ni][3]+b1);
            } else {
                // mask channels: taps n0-98, n0-97
                const int q0 = n0 - NOFF, q1 = q0 + 1;
                if (q0 < KK){
                    float b0 = biass[n0];
                    float v0 = 2.f/(1.f + __expf(-(acc[ni][0]+b0)));
                    float v2 = 2.f/(1.f + __expf(-(acc[ni][2]+b0)));
                    g_mask[q0*PIXT + pA] = __float2half_rn(v0);
                    g_mask[q0*PIXT + pB] = __float2half_rn(v2);
                }
                if (q1 < KK){
                    float b1 = biass[n0+1];
                    float v1 = 2.f/(1.f + __expf(-(acc[ni][1]+b1)));
                    float v3 = 2.f/(1.f + __expf(-(acc[ni][3]+b1)));
                    g_mask[q1*PIXT + pA] = __float2half_rn(v1);
                    g_mask[q1*PIXT + pB] = __float2half_rn(v3);
                }
            }
        }
    }
}

// ================= K2b: deformable sampling (4 lanes / pixel) =================
__global__ __launch_bounds__(256)
void dsa_deform_kernel(){
    const int gt  = blockIdx.x * 256 + threadIdx.x;  // 0..524287
    const int way = gt & 3;
    const int t   = gt >> 2;                         // pixel 0..131071
    const int b   = t >> 14;
    const int p   = t & 16383;
    const float yf = (float)(p >> 7);
    const float xf = (float)(p & 127);

    const float2* att = g_att2 + (b << 14);

    float part = 0.f;
    #pragma unroll
    for (int kk = way; kk < KK; kk += 4){
        float4  tc = __ldg(g_tapf + kk);             // (dy-3, dx-3, w0, w1)
        __half2 o2 = g_off[kk*PIXT + t];
        float2  of = __half22float2(o2);
        float   mk = __half2float(g_mask[kk*PIXT + t]);

        float py  = yf + tc.x + of.x;
        float pxx = xf + tc.y + of.y;

        float fy = floorf(py), fx = floorf(pxx);
        int y0 = (int)fy, x0 = (int)fx;
        int y1 = y0 + 1,  x1 = x0 + 1;
        float wy1 = py - fy,  wy0 = 1.f - wy1;
        float wx1 = pxx - fx, wx0 = 1.f - wx1;
        float s0 = 0.f, s1 = 0.f;
        bool yv0 = (unsigned)y0 < (unsigned)Hn, yv1 = (unsigned)y1 < (unsigned)Hn;
        bool xv0 = (unsigned)x0 < (unsigned)Wn, xv1 = (unsigned)x1 < (unsigned)Wn;
        if (yv0 && xv0){ float2 v = att[(y0<<7)+x0]; float w = wy0*wx0; s0 += w*v.x; s1 += w*v.y; }
        if (yv0 && xv1){ float2 v = att[(y0<<7)+x1]; float w = wy0*wx1; s0 += w*v.x; s1 += w*v.y; }
        if (yv1 && xv0){ float2 v = att[(y1<<7)+x0]; float w = wy1*wx0; s0 += w*v.x; s1 += w*v.y; }
        if (yv1 && xv1){ float2 v = att[(y1<<7)+x1]; float w = wy1*wx1; s0 += w*v.x; s1 += w*v.y; }

        part += (s0*tc.z + s1*tc.w) * mk;
    }
    // reduce over the 4 ways (lanes 4i..4i+3 hold the same pixel)
    part += __shfl_down_sync(0xFFFFFFFFu, part, 2);
    part += __shfl_down_sync(0xFFFFFFFFu, part, 1);
    if (way == 0)
        g_attmap[t] = 1.f/(1.f + __expf(-part));
}

// ================= K3: out = x * attmap (streaming) =================
__global__ void dsa_mul_kernel(const float* __restrict__ x,
                               float* __restrict__ out){
    int gid = blockIdx.x * 256 + threadIdx.x;       // float4 index
    float4 xv = __ldcs((const float4*)x + gid);
    int e   = gid << 2;
    int b   = e >> 22;
    int pix = e & 16383;
    float4 a = *(const float4*)(g_attmap + (b << 14) + pix);
    xv.x *= a.x; xv.y *= a.y; xv.z *= a.z; xv.w *= a.w;
    __stcs((float4*)out + gid, xv);
}

// ================= launch =================
extern "C" void kernel_launch(void* const* d_in, const int* in_sizes, int n_in,
                              void* d_out, int out_size){
    const float* x        = (const float*)d_in[0];
    const float* offset_w = (const float*)d_in[1];
    const float* offset_b = (const float*)d_in[2];
    const float* mod_w    = (const float*)d_in[3];
    const float* mod_b    = (const float*)d_in[4];
    const float* dconv_w  = (const float*)d_in[5];
    float* out = (float*)d_out;

    cudaFuncSetAttribute(dsa_conv_kernel,
                         cudaFuncAttributeMaxDynamicSharedMemorySize, SMA_TOTAL);

    dsa_prep_kernel<<<16, 512>>>(offset_w, offset_b, mod_w, mod_b, dconv_w);
    dsa_reduce_kernel<<<256, 128>>>(x);
    dsa_conv_kernel<<<Bn*Hn*2, 256, SMA_TOTAL>>>();
    dsa_deform_kernel<<<(PIXT*4)/256, 256>>>();
    dsa_mul_kernel<<<(Bn*Cn*HW/4)/256, 256>>>(x, out);
}